// round 3
// baseline (speedup 1.0000x reference)
#include <cuda_runtime.h>
#include <cstdint>

// GGNN message passing as two tf32 tensor-core GEMM stages.
// Stage1: G[(b,j)][(dirc,d)] = sum_e h[b,j,e] * W[dirc][d][e]      (32768x512x64)
// Stage2: out[b,i,dir*64+d]  = sum_{j,c} 1[adjX==c] * G[b,j,dir*4+c,d] + bias
//   dir=0: adjX = adj[b,i,j]   (m_in,  matrix_in)
//   dir=1: adjX = adj[b,j,i]   (m_out, matrix_out)
// One-hot A operand is synthesized in registers (exact in tf32).

#define NB 32
#define NN 1024

__device__ float g_scratch[(size_t)NB * NN * 512];  // [b*1024+j][dirc*64+d]

__device__ __forceinline__ uint32_t f2tf(float x) {
    uint32_t r;
    asm("cvt.rna.tf32.f32 %0, %1;" : "=r"(r) : "f"(x));
    return r;
}

__device__ __forceinline__ void mma8(float* d,
                                     uint32_t a0, uint32_t a1, uint32_t a2, uint32_t a3,
                                     uint32_t b0, uint32_t b1) {
    asm volatile("mma.sync.aligned.m16n8k8.row.col.f32.tf32.tf32.f32 "
                 "{%0,%1,%2,%3}, {%4,%5,%6,%7}, {%8,%9}, {%0,%1,%2,%3};"
                 : "+f"(d[0]), "+f"(d[1]), "+f"(d[2]), "+f"(d[3])
                 : "r"(a0), "r"(a1), "r"(a2), "r"(a3), "r"(b0), "r"(b1));
}

// ---------------------------------------------------------------------------
// Stage 1: grid (512 m-tiles of 64 (b,j)-rows, 8 dirc), 128 threads (4 warps).
// ---------------------------------------------------------------------------
__global__ __launch_bounds__(128) void ggnn_stage1(const float* __restrict__ h,
                                                   const float* __restrict__ Win,
                                                   const float* __restrict__ Wout) {
    __shared__ uint32_t hs[64 * 68];   // [row][e], stride 68
    __shared__ uint32_t ws[64 * 72];   // [e][d],  stride 72
    const int mtile = blockIdx.x;      // 0..511
    const int dirc  = blockIdx.y;      // 0..7
    const int t = threadIdx.x;
    const float* W = (dirc < 4) ? (Win + dirc * 4096) : (Wout + (dirc - 4) * 4096);

    const float* hbase = h + (size_t)mtile * 64 * 64;
#pragma unroll
    for (int q = 0; q < 8; q++) {
        int f4 = t + q * 128;                 // 1024 float4s
        int row = f4 >> 4, e4 = (f4 & 15) * 4;
        float4 v = *(const float4*)(hbase + row * 64 + e4);
        uint4 u = make_uint4(f2tf(v.x), f2tf(v.y), f2tf(v.z), f2tf(v.w));
        *(uint4*)(hs + row * 68 + e4) = u;
    }
#pragma unroll
    for (int q = 0; q < 8; q++) {             // ws[e][d] = W[d][e] (transpose)
        int f4 = t + q * 128;
        int d = f4 >> 4, e4 = (f4 & 15) * 4;
        float4 v = *(const float4*)(W + d * 64 + e4);
        ws[(e4 + 0) * 72 + d] = f2tf(v.x);
        ws[(e4 + 1) * 72 + d] = f2tf(v.y);
        ws[(e4 + 2) * 72 + d] = f2tf(v.z);
        ws[(e4 + 3) * 72 + d] = f2tf(v.w);
    }
    __syncthreads();

    const int warp = t >> 5, lane = t & 31;
    const int g = lane >> 2, tig = lane & 3;
    const int r0 = warp * 16 + g;

    float acc[8][4];
#pragma unroll
    for (int nt = 0; nt < 8; nt++)
#pragma unroll
        for (int k = 0; k < 4; k++) acc[nt][k] = 0.f;

#pragma unroll
    for (int ks = 0; ks < 8; ks++) {
        int e0 = ks * 8;
        uint32_t a0 = hs[r0 * 68 + e0 + tig];
        uint32_t a1 = hs[(r0 + 8) * 68 + e0 + tig];
        uint32_t a2 = hs[r0 * 68 + e0 + tig + 4];
        uint32_t a3 = hs[(r0 + 8) * 68 + e0 + tig + 4];
#pragma unroll
        for (int nt = 0; nt < 8; nt++) {
            uint32_t b0 = ws[(e0 + tig) * 72 + nt * 8 + g];
            uint32_t b1 = ws[(e0 + tig + 4) * 72 + nt * 8 + g];
            mma8(acc[nt], a0, a1, a2, a3, b0, b1);
        }
    }

    size_t row0 = (size_t)mtile * 64 + warp * 16 + g;
#pragma unroll
    for (int nt = 0; nt < 8; nt++) {
        size_t col = (size_t)dirc * 64 + nt * 8 + tig * 2;
        *(float2*)(g_scratch + row0 * 512 + col)       = make_float2(acc[nt][0], acc[nt][1]);
        *(float2*)(g_scratch + (row0 + 8) * 512 + col) = make_float2(acc[nt][2], acc[nt][3]);
    }
}

// ---------------------------------------------------------------------------
// Stage 2: grid (8 m-tiles, 2 dirs, 32 batches), 256 threads (8 warps).
// Each block: C[128 x 64] += A[128 x 4096(one-hot)] * G[4096 x 64].
// ---------------------------------------------------------------------------
__global__ __launch_bounds__(256) void ggnn_stage2(const int* __restrict__ adj,
                                                   const float* __restrict__ bias,
                                                   float* __restrict__ out) {
    __shared__ uint32_t gs[64 * 72];   // [kk][d], kk = jj*4+c (16 j per chunk)
    __shared__ int adjs[128 * 17];     // [i_local][jj], stride 17
    const int mtile = blockIdx.x;      // 0..7
    const int dir   = blockIdx.y;      // 0..1
    const int b     = blockIdx.z;      // 0..31
    const int t = threadIdx.x;
    const int warp = t >> 5, lane = t & 31;
    const int g = lane >> 2, tig = lane & 3;
    const int mbase = mtile * 128;
    const int rloc = warp * 16 + g;

    float acc[8][4];
#pragma unroll
    for (int nt = 0; nt < 8; nt++)
#pragma unroll
        for (int k = 0; k < 4; k++) acc[nt][k] = 0.f;

    const float* gb = g_scratch + (size_t)b * 1024 * 512 + dir * 256;
    const int* adjb = adj + (size_t)b * 1024 * 1024;

    for (int ch = 0; ch < 64; ch++) {
        const int j0 = ch * 16;
        __syncthreads();
        // stage G chunk: gs[kk][d], kk = jj*4 + c
#pragma unroll
        for (int q = 0; q < 4; q++) {
            int f4 = t + q * 256;                 // 1024 float4s
            int kk = f4 >> 4, d4 = (f4 & 15) * 4;
            const float* src = gb + (size_t)(j0 + (kk >> 2)) * 512 + (kk & 3) * 64 + d4;
            float4 v = *(const float4*)src;
            uint4 u = make_uint4(f2tf(v.x), f2tf(v.y), f2tf(v.z), f2tf(v.w));
            *(uint4*)(gs + kk * 72 + d4) = u;
        }
        // stage adjacency chunk
        if (dir == 0) {
#pragma unroll
            for (int q = 0; q < 8; q++) {
                int l = t + q * 256;              // 2048 ints
                int r = l >> 4, jj = l & 15;
                adjs[r * 17 + jj] = adjb[(size_t)(mbase + r) * 1024 + j0 + jj];
            }
        } else {
#pragma unroll
            for (int q = 0; q < 8; q++) {
                int l = t + q * 256;
                int jj = l >> 7, r = l & 127;
                adjs[r * 17 + jj] = adjb[(size_t)(j0 + jj) * 1024 + mbase + r];
            }
        }
        __syncthreads();

#pragma unroll
        for (int ks = 0; ks < 8; ks++) {
            const int kk0 = ks * 8;
            const int jj0 = ks * 2;
            int v0 = adjs[rloc * 17 + jj0];
            int v1 = adjs[(rloc + 8) * 17 + jj0];
            int v2 = adjs[rloc * 17 + jj0 + 1];
            int v3 = adjs[(rloc + 8) * 17 + jj0 + 1];
            uint32_t a0 = (v0 == tig) ? 0x3F800000u : 0u;
            uint32_t a1 = (v1 == tig) ? 0x3F800000u : 0u;
            uint32_t a2 = (v2 == tig) ? 0x3F800000u : 0u;
            uint32_t a3 = (v3 == tig) ? 0x3F800000u : 0u;
#pragma unroll
            for (int nt = 0; nt < 8; nt++) {
                uint32_t b0 = gs[(kk0 + tig) * 72 + nt * 8 + g];
                uint32_t b1 = gs[(kk0 + tig + 4) * 72 + nt * 8 + g];
                mma8(acc[nt], a0, a1, a2, a3, b0, b1);
            }
        }
    }

    // epilogue: out[b, i, dir*64 + n] = acc + bias
    const int i0 = mbase + rloc;
#pragma unroll
    for (int nt = 0; nt < 8; nt++) {
        int n = dir * 64 + nt * 8 + tig * 2;
        float2 bv = *(const float2*)(bias + n);
        float* o0 = out + ((size_t)b * 1024 + i0) * 128 + n;
        float* o1 = out + ((size_t)b * 1024 + i0 + 8) * 128 + n;
        *(float2*)o0 = make_float2(acc[nt][0] + bv.x, acc[nt][1] + bv.y);
        *(float2*)o1 = make_float2(acc[nt][2] + bv.x, acc[nt][3] + bv.y);
    }
}

extern "C" void kernel_launch(void* const* d_in, const int* in_sizes, int n_in,
                              void* d_out, int out_size) {
    (void)in_sizes; (void)n_in; (void)out_size;
    const float* h    = (const float*)d_in[0];
    const int*   adj  = (const int*)d_in[1];
    const float* Win  = (const float*)d_in[2];
    const float* Wout = (const float*)d_in[3];
    const float* bias = (const float*)d_in[4];
    float* out = (float*)d_out;

    ggnn_stage1<<<dim3(512, 8), 128>>>(h, Win, Wout);
    ggnn_stage2<<<dim3(8, 2, 32), 256>>>(adj, bias, out);
}

// round 4
// speedup vs baseline: 1.6259x; 1.6259x over previous
#include <cuda_runtime.h>
#include <cstdint>

// GGNN message passing, two tf32 tensor-core GEMM stages.
// Stage1: G[(b,j)][dirc*64+d] = sum_e h[b,j,e] * W[dirc][d][e]   (32768x512x64)
//         output pre-rounded to tf32 bit pattern.
// Stage2: out[b,i,dir*64+d] = sum_{j,c} 1[adjX==c] * G[b,j,dir*4+c,d] + bias
//   dir=0: adjX = adj[b,i,j], dir=1: adjX = adj[b,j,i]
// Stage2 is cp.async double-buffered; one-hot A synthesized in registers.

#define NB 32
#define NN 1024

__device__ float g_scratch[(size_t)NB * NN * 512];  // [b*1024+j][dirc*64+d], tf32 bits

__device__ __forceinline__ uint32_t f2tf(float x) {
    uint32_t r;
    asm("cvt.rna.tf32.f32 %0, %1;" : "=r"(r) : "f"(x));
    return r;
}

__device__ __forceinline__ void mma8(float* d,
                                     uint32_t a0, uint32_t a1, uint32_t a2, uint32_t a3,
                                     uint32_t b0, uint32_t b1) {
    asm volatile("mma.sync.aligned.m16n8k8.row.col.f32.tf32.tf32.f32 "
                 "{%0,%1,%2,%3}, {%4,%5,%6,%7}, {%8,%9}, {%0,%1,%2,%3};"
                 : "+f"(d[0]), "+f"(d[1]), "+f"(d[2]), "+f"(d[3])
                 : "r"(a0), "r"(a1), "r"(a2), "r"(a3), "r"(b0), "r"(b1));
}

__device__ __forceinline__ void cpa16(uint32_t daddr, const void* gaddr) {
    asm volatile("cp.async.cg.shared.global [%0], [%1], 16;" :: "r"(daddr), "l"(gaddr));
}
__device__ __forceinline__ void cpa_commit() {
    asm volatile("cp.async.commit_group;" ::: "memory");
}
template <int N>
__device__ __forceinline__ void cpa_wait() {
    asm volatile("cp.async.wait_group %0;" :: "n"(N) : "memory");
}

// ---------------------------------------------------------------------------
// Stage 1: grid (512 m-tiles of 64 (b,j)-rows, 8 dirc), 128 threads (4 warps).
// ---------------------------------------------------------------------------
__global__ __launch_bounds__(128) void ggnn_stage1(const float* __restrict__ h,
                                                   const float* __restrict__ Win,
                                                   const float* __restrict__ Wout) {
    __shared__ uint32_t hs[64 * 68];   // [row][e], stride 68
    __shared__ uint32_t ws[64 * 72];   // [e][d],  stride 72
    const int mtile = blockIdx.x;
    const int dirc  = blockIdx.y;
    const int t = threadIdx.x;
    const float* W = (dirc < 4) ? (Win + dirc * 4096) : (Wout + (dirc - 4) * 4096);

    const float* hbase = h + (size_t)mtile * 64 * 64;
#pragma unroll
    for (int q = 0; q < 8; q++) {
        int f4 = t + q * 128;
        int row = f4 >> 4, e4 = (f4 & 15) * 4;
        float4 v = *(const float4*)(hbase + row * 64 + e4);
        uint4 u = make_uint4(f2tf(v.x), f2tf(v.y), f2tf(v.z), f2tf(v.w));
        *(uint4*)(hs + row * 68 + e4) = u;
    }
#pragma unroll
    for (int q = 0; q < 8; q++) {             // ws[e][d] = W[d][e]
        int f4 = t + q * 128;
        int d = f4 >> 4, e4 = (f4 & 15) * 4;
        float4 v = *(const float4*)(W + d * 64 + e4);
        ws[(e4 + 0) * 72 + d] = f2tf(v.x);
        ws[(e4 + 1) * 72 + d] = f2tf(v.y);
        ws[(e4 + 2) * 72 + d] = f2tf(v.z);
        ws[(e4 + 3) * 72 + d] = f2tf(v.w);
    }
    __syncthreads();

    const int warp = t >> 5, lane = t & 31;
    const int g = lane >> 2, tig = lane & 3;
    const int r0 = warp * 16 + g;

    float acc[8][4];
#pragma unroll
    for (int nt = 0; nt < 8; nt++)
#pragma unroll
        for (int k = 0; k < 4; k++) acc[nt][k] = 0.f;

#pragma unroll
    for (int ks = 0; ks < 8; ks++) {
        int e0 = ks * 8;
        uint32_t a0 = hs[r0 * 68 + e0 + tig];
        uint32_t a1 = hs[(r0 + 8) * 68 + e0 + tig];
        uint32_t a2 = hs[r0 * 68 + e0 + tig + 4];
        uint32_t a3 = hs[(r0 + 8) * 68 + e0 + tig + 4];
#pragma unroll
        for (int nt = 0; nt < 8; nt++) {
            uint32_t b0 = ws[(e0 + tig) * 72 + nt * 8 + g];
            uint32_t b1 = ws[(e0 + tig + 4) * 72 + nt * 8 + g];
            mma8(acc[nt], a0, a1, a2, a3, b0, b1);
        }
    }

    // store pre-rounded to tf32 (stage2 stages these bits raw via cp.async)
    size_t row0 = (size_t)mtile * 64 + warp * 16 + g;
    uint32_t* gout = (uint32_t*)g_scratch;
#pragma unroll
    for (int nt = 0; nt < 8; nt++) {
        size_t col = (size_t)dirc * 64 + nt * 8 + tig * 2;
        *(uint2*)(gout + row0 * 512 + col)       = make_uint2(f2tf(acc[nt][0]), f2tf(acc[nt][1]));
        *(uint2*)(gout + (row0 + 8) * 512 + col) = make_uint2(f2tf(acc[nt][2]), f2tf(acc[nt][3]));
    }
}

// ---------------------------------------------------------------------------
// Stage 2: grid (8 mtiles, 2 dirs, 32 batches), 128 threads (4 warps).
// Tile: C[128 x 64] += onehot(adj)[128 x 4096] * G[4096 x 64].
// Each warp owns 32 rows = two m16 row-blocks sharing B fragments.
// Double-buffered cp.async pipeline; dynamic smem:
//   gs[2][64*68]  (G chunk, kk = jj*4+c, stride 68)
//   as[2][2560]   (adj chunk; dir0: [r][jj] stride 20; dir1: [jj][r] stride 132)
// ---------------------------------------------------------------------------
#define GS_STRIDE 68
#define GS_WORDS  (64 * GS_STRIDE)      // 4352
#define AS_WORDS  2560
#define SM2_WORDS (2 * (GS_WORDS + AS_WORDS))  // 13824 words = 55296 B

__global__ __launch_bounds__(128, 4) void ggnn_stage2(const int* __restrict__ adj,
                                                      const float* __restrict__ bias,
                                                      float* __restrict__ out) {
    extern __shared__ uint32_t sm[];
    uint32_t* gsb[2] = { sm, sm + GS_WORDS };
    uint32_t* asb[2] = { sm + 2 * GS_WORDS, sm + 2 * GS_WORDS + AS_WORDS };

    const int mtile = blockIdx.x;
    const int dir   = blockIdx.y;
    const int b     = blockIdx.z;
    const int t = threadIdx.x;
    const int warp = t >> 5, lane = t & 31;
    const int g = lane >> 2, tig = lane & 3;
    const int mbase = mtile * 128;
    const int r0 = warp * 32 + g;
    // unified adj indexing: value(r, jj) = as[r*rs + jj*js]
    const int rs = dir ? 1 : 20;
    const int js = dir ? 132 : 1;

    const uint32_t* gb = (const uint32_t*)g_scratch + (size_t)b * 1024 * 512 + dir * 256;
    const int* adjb = adj + (size_t)b * 1024 * 1024;

    float acc[2][8][4];
#pragma unroll
    for (int rb = 0; rb < 2; rb++)
#pragma unroll
        for (int nt = 0; nt < 8; nt++)
#pragma unroll
            for (int k = 0; k < 4; k++) acc[rb][nt][k] = 0.f;

    // --- async staging of one chunk ---
    auto issue = [&](int ch, int buf) {
        const int j0 = ch * 16;
        uint32_t gdst = (uint32_t)__cvta_generic_to_shared(gsb[buf]);
        uint32_t adst = (uint32_t)__cvta_generic_to_shared(asb[buf]);
        // G: 64 kk-rows x 64 words, kk = jj*4+c
#pragma unroll
        for (int q = 0; q < 8; q++) {
            int idx = t + q * 128;
            int kk = idx >> 4, d4 = (idx & 15) * 4;
            const uint32_t* src = gb + (size_t)(j0 + (kk >> 2)) * 512 + (kk & 3) * 64 + d4;
            cpa16(gdst + (kk * GS_STRIDE + d4) * 4, src);
        }
        if (dir == 0) {  // [r][jj], stride 20: rows of adj, 16 ints each
#pragma unroll
            for (int q = 0; q < 4; q++) {
                int idx = t + q * 128;
                int r = idx >> 2, c4 = (idx & 3) * 4;
                cpa16(adst + (r * 20 + c4) * 4, adjb + (size_t)(mbase + r) * 1024 + j0 + c4);
            }
        } else {         // [jj][r], stride 132: contiguous 128-int row slices
#pragma unroll
            for (int q = 0; q < 4; q++) {
                int idx = t + q * 128;
                int jj = idx >> 5, r4 = (idx & 31) * 4;
                cpa16(adst + (jj * 132 + r4) * 4, adjb + (size_t)(j0 + jj) * 1024 + mbase + r4);
            }
        }
        cpa_commit();
    };

    issue(0, 0);

#pragma unroll 1
    for (int ch = 0; ch < 64; ch++) {
        if (ch < 63) {
            issue(ch + 1, (ch + 1) & 1);
            cpa_wait<1>();
        } else {
            cpa_wait<0>();
        }
        __syncthreads();

        const uint32_t* gs = gsb[ch & 1];
        const int* as_ = (const int*)asb[ch & 1];

#pragma unroll
        for (int ks = 0; ks < 8; ks++) {
            const int kk0 = ks * 8;
            const int jj0 = ks * 2;
            const int base = r0 * rs + jj0 * js;
            int v00 = as_[base];
            int v01 = as_[base + 8 * rs];
            int v02 = as_[base + js];
            int v03 = as_[base + 8 * rs + js];
            int v10 = as_[base + 16 * rs];
            int v11 = as_[base + 24 * rs];
            int v12 = as_[base + 16 * rs + js];
            int v13 = as_[base + 24 * rs + js];
            uint32_t a00 = (v00 == tig) ? 0x3F800000u : 0u;
            uint32_t a01 = (v01 == tig) ? 0x3F800000u : 0u;
            uint32_t a02 = (v02 == tig) ? 0x3F800000u : 0u;
            uint32_t a03 = (v03 == tig) ? 0x3F800000u : 0u;
            uint32_t a10 = (v10 == tig) ? 0x3F800000u : 0u;
            uint32_t a11 = (v11 == tig) ? 0x3F800000u : 0u;
            uint32_t a12 = (v12 == tig) ? 0x3F800000u : 0u;
            uint32_t a13 = (v13 == tig) ? 0x3F800000u : 0u;
#pragma unroll
            for (int nt = 0; nt < 8; nt++) {
                uint32_t b0 = gs[(kk0 + tig) * GS_STRIDE + nt * 8 + g];
                uint32_t b1 = gs[(kk0 + tig + 4) * GS_STRIDE + nt * 8 + g];
                mma8(acc[0][nt], a00, a01, a02, a03, b0, b1);
                mma8(acc[1][nt], a10, a11, a12, a13, b0, b1);
            }
        }
        __syncthreads();
    }

    // epilogue: out[b, i, dir*64 + n] = acc + bias
#pragma unroll
    for (int rb = 0; rb < 2; rb++) {
        const int i0 = mbase + r0 + rb * 16;
#pragma unroll
        for (int nt = 0; nt < 8; nt++) {
            int n = dir * 64 + nt * 8 + tig * 2;
            float2 bv = *(const float2*)(bias + n);
            float* o0 = out + ((size_t)b * 1024 + i0) * 128 + n;
            float* o1 = out + ((size_t)b * 1024 + i0 + 8) * 128 + n;
            *(float2*)o0 = make_float2(acc[rb][nt][0] + bv.x, acc[rb][nt][1] + bv.y);
            *(float2*)o1 = make_float2(acc[rb][nt][2] + bv.x, acc[rb][nt][3] + bv.y);
        }
    }
}

extern "C" void kernel_launch(void* const* d_in, const int* in_sizes, int n_in,
                              void* d_out, int out_size) {
    (void)in_sizes; (void)n_in; (void)out_size;
    const float* h    = (const float*)d_in[0];
    const int*   adj  = (const int*)d_in[1];
    const float* Win  = (const float*)d_in[2];
    const float* Wout = (const float*)d_in[3];
    const float* bias = (const float*)d_in[4];
    float* out = (float*)d_out;

    static bool attr_set = false;
    if (!attr_set) {
        cudaFuncSetAttribute(ggnn_stage2, cudaFuncAttributeMaxDynamicSharedMemorySize,
                             SM2_WORDS * 4);
        attr_set = true;
    }

    ggnn_stage1<<<dim3(512, 8), 128>>>(h, Win, Wout);
    ggnn_stage2<<<dim3(8, 2, 32), 128, SM2_WORDS * 4>>>(adj, bias, out);
}

// round 6
// speedup vs baseline: 1.8848x; 1.1593x over previous
#include <cuda_runtime.h>
#include <cstdint>

// GGNN message passing, two tf32 tensor-core GEMM stages.
// Stage1: G[b,j,dirc,d] = sum_e h[b,j,e]*W[dirc][d][e], written tf32-rounded into
//         blob layout [b][dir][ch][kk][p]  (ch=j>>4, kk=(j&15)*4+c, p=(d&7)*8+(d>>3))
// Stage2: out[b,i,dir*64+d] = sum_{j,c} 1[adjX==c]*G[...] + bias, one-hot A in regs.
//   dir=0: adjX=adj[b,i,j]; dir=1: adjX=adj[b,j,i].
// Permuted-K: mma-k slot s <-> kk = kk0 + 4*(s>>1) + 2*(s&1) (+1 for s+4): one adj
// element serves both k-slots of a thread; even/odd kk rows split so b0/b1 come
// from separate rows. Permuted-N: thread's 8 B-values per row contiguous -> LDS.128.

__device__ uint32_t g_scratch[(size_t)32 * 2 * 64 * 64 * 64];  // 64 MB

__device__ __forceinline__ uint32_t f2tf(float x) {
    uint32_t r;
    asm("cvt.rna.tf32.f32 %0, %1;" : "=r"(r) : "f"(x));
    return r;
}

__device__ __forceinline__ void mma8(float* d,
                                     uint32_t a0, uint32_t a1, uint32_t a2, uint32_t a3,
                                     uint32_t b0, uint32_t b1) {
    asm volatile("mma.sync.aligned.m16n8k8.row.col.f32.tf32.tf32.f32 "
                 "{%0,%1,%2,%3}, {%4,%5,%6,%7}, {%8,%9}, {%0,%1,%2,%3};"
                 : "+f"(d[0]), "+f"(d[1]), "+f"(d[2]), "+f"(d[3])
                 : "r"(a0), "r"(a1), "r"(a2), "r"(a3), "r"(b0), "r"(b1));
}

__device__ __forceinline__ void cpa16(uint32_t daddr, const void* gaddr) {
    asm volatile("cp.async.cg.shared.global [%0], [%1], 16;" :: "r"(daddr), "l"(gaddr));
}
__device__ __forceinline__ void cpa_commit() {
    asm volatile("cp.async.commit_group;" ::: "memory");
}
template <int N>
__device__ __forceinline__ void cpa_wait() {
    asm volatile("cp.async.wait_group %0;" :: "n"(N) : "memory");
}

// ---------------------------------------------------------------------------
// Stage 1: grid 512 (64-row tiles of (b,j)), 128 threads. h read once; loop dirc.
// ---------------------------------------------------------------------------
__global__ __launch_bounds__(128) void ggnn_stage1(const float* __restrict__ h,
                                                   const float* __restrict__ Win,
                                                   const float* __restrict__ Wout) {
    __shared__ uint32_t hs[64 * 68];   // [row][e]
    __shared__ uint32_t wo[64 * 72];   // ws [e][d] stride 72 / outs [lj][p] stride 68
    const int mtile = blockIdx.x;
    const int t = threadIdx.x;
    const int warp = t >> 5, lane = t & 31;
    const int g = lane >> 2, tig = lane & 3;
    const int r0 = warp * 16 + g;

    const float* hbase = h + (size_t)mtile * 64 * 64;
#pragma unroll
    for (int q = 0; q < 8; q++) {
        int f4 = t + q * 128;
        int row = f4 >> 4, e4 = (f4 & 15) * 4;
        float4 v = *(const float4*)(hbase + row * 64 + e4);
        uint4 u = make_uint4(f2tf(v.x), f2tf(v.y), f2tf(v.z), f2tf(v.w));
        *(uint4*)(hs + row * 68 + e4) = u;
    }
    __syncthreads();

    const int b = mtile >> 4;
    const int mtl = mtile & 15;

#pragma unroll 1
    for (int dirc = 0; dirc < 8; dirc++) {
        const float* W = (dirc < 4) ? (Win + dirc * 4096) : (Wout + (dirc - 4) * 4096);
        // ws[e][d] = W[d][e], stride 72
#pragma unroll
        for (int q = 0; q < 8; q++) {
            int f4 = t + q * 128;
            int d = f4 >> 4, e4 = (f4 & 15) * 4;
            float4 v = *(const float4*)(W + d * 64 + e4);
            wo[(e4 + 0) * 72 + d] = f2tf(v.x);
            wo[(e4 + 1) * 72 + d] = f2tf(v.y);
            wo[(e4 + 2) * 72 + d] = f2tf(v.z);
            wo[(e4 + 3) * 72 + d] = f2tf(v.w);
        }
        __syncthreads();

        float acc[8][4];
#pragma unroll
        for (int nt = 0; nt < 8; nt++)
#pragma unroll
            for (int k = 0; k < 4; k++) acc[nt][k] = 0.f;

#pragma unroll
        for (int ks = 0; ks < 8; ks++) {
            int e0 = ks * 8;
            uint32_t a0 = hs[r0 * 68 + e0 + tig];
            uint32_t a1 = hs[(r0 + 8) * 68 + e0 + tig];
            uint32_t a2 = hs[r0 * 68 + e0 + tig + 4];
            uint32_t a3 = hs[(r0 + 8) * 68 + e0 + tig + 4];
#pragma unroll
            for (int nt = 0; nt < 8; nt++) {
                uint32_t b0 = wo[(e0 + tig) * 72 + nt * 8 + g];
                uint32_t b1 = wo[(e0 + tig + 4) * 72 + nt * 8 + g];
                mma8(acc[nt], a0, a1, a2, a3, b0, b1);
            }
        }
        __syncthreads();  // done reading ws

        // stage output tile permuted: outs[lj][p], p = (d&7)*8 + (d>>3)
#pragma unroll
        for (int nt = 0; nt < 8; nt++) {
            wo[r0 * 68 + 16 * tig + nt]           = f2tf(acc[nt][0]);
            wo[r0 * 68 + 16 * tig + 8 + nt]       = f2tf(acc[nt][1]);
            wo[(r0 + 8) * 68 + 16 * tig + nt]     = f2tf(acc[nt][2]);
            wo[(r0 + 8) * 68 + 16 * tig + 8 + nt] = f2tf(acc[nt][3]);
        }
        __syncthreads();

        // dump to blob: [b][dir][ch][kk][64]
        const int dir = dirc >> 2, c = dirc & 3;
        uint32_t* blob = g_scratch + ((size_t)(b * 2 + dir) << 18);
#pragma unroll
        for (int q = 0; q < 8; q++) {
            int idx4 = t + q * 128;          // 1024 16B units
            int lj = idx4 >> 4, u = idx4 & 15;
            int ch = mtl * 4 + (lj >> 4);
            int kk = (lj & 15) * 4 + c;
            uint4 val = *(uint4*)(wo + lj * 68 + u * 4);
            *(uint4*)(blob + (size_t)ch * 4096 + kk * 64 + u * 4) = val;
        }
        __syncthreads();
    }
}

// ---------------------------------------------------------------------------
// Stage 2: grid (8 mtiles, 2 dirs, 32 b), 128 threads (4 warps x 32 rows).
// smem per buffer: gs 64 rows x 68 words (even kk -> rows 0..31, odd -> 32..63),
// adj 2560 words (dir0: [r][jj] stride 20; dir1: [jj][r] stride 132).
// ---------------------------------------------------------------------------
#define GS_W  (64 * 68)                 // 4352
#define AS_W  2560
#define BUF_W (GS_W + AS_W)             // 6912
#define SM2_W (2 * BUF_W)               // 13824 words = 55296 B (dynamic)

__global__ __launch_bounds__(128, 4) void ggnn_stage2(const int* __restrict__ adj,
                                                      const float* __restrict__ bias,
                                                      float* __restrict__ out) {
    extern __shared__ uint32_t sm[];

    const int mtile = blockIdx.x;
    const int dir   = blockIdx.y;
    const int b     = blockIdx.z;
    const int t = threadIdx.x;
    const int warp = t >> 5, lane = t & 31;
    const int g = lane >> 2, tig = lane & 3;
    const int mbase = mtile * 128;
    const int rw = warp * 32;            // warp's first row
    const int ca = (tig & 1) * 2;        // classes ca, ca+1
    const int jb = tig >> 1;             // jj offset 0/1
    const int rs = dir ? 1 : 20;         // adj: v(row,jj) = as_[row*rs + jj*js]
    const int js = dir ? 132 : 1;

    const uint32_t* blob = g_scratch + ((size_t)(b * 2 + dir) << 18);
    const int* adjb = adj + (size_t)b * 1024 * 1024;

    float acc[2][8][4];
#pragma unroll
    for (int rb = 0; rb < 2; rb++)
#pragma unroll
        for (int nt = 0; nt < 8; nt++)
#pragma unroll
            for (int k = 0; k < 4; k++) acc[rb][nt][k] = 0.f;

    auto issue = [&](int ch, int buf) {
        const int j0 = ch * 16;
        uint32_t gdst = (uint32_t)__cvta_generic_to_shared(sm + buf * BUF_W);
        uint32_t adst = gdst + GS_W * 4;
        const uint32_t* gsrc = blob + (size_t)ch * 4096;
        // G chunk: 1024 16B units; row kk -> smem row rr=(kk>>1)+(kk&1)*32, stride 68
#pragma unroll
        for (int q = 0; q < 8; q++) {
            int idx = t + q * 128;
            int kk = idx >> 4, u4 = (idx & 15) * 4;
            int rr = (kk >> 1) + (kk & 1) * 32;
            cpa16(gdst + (rr * 68 + u4) * 4, gsrc + kk * 64 + u4);
        }
        if (dir == 0) {      // [r][jj] stride 20
#pragma unroll
            for (int q = 0; q < 4; q++) {
                int idx = t + q * 128;
                int r = idx >> 2, c4 = (idx & 3) * 4;
                cpa16(adst + (r * 20 + c4) * 4, adjb + (size_t)(mbase + r) * 1024 + j0 + c4);
            }
        } else {             // [jj][r] stride 132
#pragma unroll
            for (int q = 0; q < 4; q++) {
                int idx = t + q * 128;
                int jj = idx >> 5, r4 = (idx & 31) * 4;
                cpa16(adst + (jj * 132 + r4) * 4, adjb + (size_t)(j0 + jj) * 1024 + mbase + r4);
            }
        }
        cpa_commit();
    };

    issue(0, 0);

#pragma unroll 1
    for (int ch = 0; ch < 64; ch++) {
        if (ch < 63) {
            issue(ch + 1, (ch + 1) & 1);
            cpa_wait<1>();
        } else {
            cpa_wait<0>();
        }
        __syncthreads();

        const uint32_t* gs = sm + (ch & 1) * BUF_W;
        const int* as_ = (const int*)(gs + GS_W);

#pragma unroll
        for (int ks = 0; ks < 8; ks++) {
            const int jj = 2 * ks + jb;
            const int* ap = as_ + jj * js + rw * rs;
            int v0 = ap[g * rs];
            int v1 = ap[(g + 8) * rs];
            int v2 = ap[(g + 16) * rs];
            int v3 = ap[(g + 24) * rs];
            uint32_t a00 = (v0 == ca)     ? 0x3F800000u : 0u;
            uint32_t a01 = (v1 == ca)     ? 0x3F800000u : 0u;
            uint32_t a02 = (v0 == ca + 1) ? 0x3F800000u : 0u;
            uint32_t a03 = (v1 == ca + 1) ? 0x3F800000u : 0u;
            uint32_t a10 = (v2 == ca)     ? 0x3F800000u : 0u;
            uint32_t a11 = (v3 == ca)     ? 0x3F800000u : 0u;
            uint32_t a12 = (v2 == ca + 1) ? 0x3F800000u : 0u;
            uint32_t a13 = (v3 == ca + 1) ? 0x3F800000u : 0u;

            // even kk row (b0s) at rr = 4ks+tig; odd kk row (b1s) at +32 rows
            const uint32_t* bpa = gs + (4 * ks + tig) * 68 + 8 * g;
            const uint32_t* bpb = bpa + 32 * 68;
#pragma unroll
            for (int mp = 0; mp < 2; mp++) {
                uint4 B0 = *(const uint4*)(bpa + 4 * mp);   // nt = 4mp..4mp+3, b0
                uint4 B1 = *(const uint4*)(bpb + 4 * mp);   // b1
                mma8(acc[0][4 * mp + 0], a00, a01, a02, a03, B0.x, B1.x);
                mma8(acc[0][4 * mp + 1], a00, a01, a02, a03, B0.y, B1.y);
                mma8(acc[0][4 * mp + 2], a00, a01, a02, a03, B0.z, B1.z);
                mma8(acc[0][4 * mp + 3], a00, a01, a02, a03, B0.w, B1.w);
                mma8(acc[1][4 * mp + 0], a10, a11, a12, a13, B0.x, B1.x);
                mma8(acc[1][4 * mp + 1], a10, a11, a12, a13, B0.y, B1.y);
                mma8(acc[1][4 * mp + 2], a10, a11, a12, a13, B0.z, B1.z);
                mma8(acc[1][4 * mp + 3], a10, a11, a12, a13, B0.w, B1.w);
            }
        }
        __syncthreads();
    }

    // epilogue
#pragma unroll
    for (int rb = 0; rb < 2; rb++) {
        const int i0 = mbase + rw + rb * 16 + g;
#pragma unroll
        for (int nt = 0; nt < 8; nt++) {
            int n = dir * 64 + nt * 8 + tig * 2;
            float2 bv = *(const float2*)(bias + n);
            float* o0 = out + ((size_t)b * 1024 + i0) * 128 + n;
            float* o1 = out + ((size_t)b * 1024 + i0 + 8) * 128 + n;
            *(float2*)o0 = make_float2(acc[rb][nt][0] + bv.x, acc[rb][nt][1] + bv.y);
            *(float2*)o1 = make_float2(acc[rb][nt][2] + bv.x, acc[rb][nt][3] + bv.y);
        }
    }
}

extern "C" void kernel_launch(void* const* d_in, const int* in_sizes, int n_in,
                              void* d_out, int out_size) {
    (void)in_sizes; (void)n_in; (void)out_size;
    const float* h    = (const float*)d_in[0];
    const int*   adj  = (const int*)d_in[1];
    const float* Win  = (const float*)d_in[2];
    const float* Wout = (const float*)d_in[3];
    const float* bias = (const float*)d_in[4];
    float* out = (float*)d_out;

    cudaFuncSetAttribute(ggnn_stage2, cudaFuncAttributeMaxDynamicSharedMemorySize,
                         SM2_W * 4);

    ggnn_stage1<<<512, 128>>>(h, Win, Wout);
    ggnn_stage2<<<dim3(8, 2, 32), 128, SM2_W * 4>>>(adj, bias, out);
}

// round 7
// speedup vs baseline: 1.8857x; 1.0004x over previous
#include <cuda_runtime.h>
#include <cstdint>

// GGNN message passing, two tf32 tensor-core GEMM stages.
// Stage1: G[b,j,dirc,d] = sum_e h[b,j,e]*W[dirc][d][e], written tf32-rounded into
//         blob layout [b][dir][ch][kk][p]  (ch=j>>4, kk=(j&15)*4+c, p=(d&7)*8+(d>>3))
// Stage2: out[b,i,dir*64+d] = sum_{j,c} 1[adjX==c]*G[...] + bias, one-hot A in regs.
//   dir=0: adjX=adj[b,i,j]; dir=1: adjX=adj[b,j,i].
// Permuted-K: mma-k slot s <-> kk = kk0 + 4*(s>>1) + 2*(s&1) (+1 for s+4): one adj
// element serves both k-slots of a thread; even/odd kk rows split so b0/b1 come
// from separate rows. Permuted-N: thread's 8 B-values per row contiguous -> LDS.128.

__device__ uint32_t g_scratch[(size_t)32 * 2 * 64 * 64 * 64];  // 64 MB

__device__ __forceinline__ uint32_t f2tf(float x) {
    uint32_t r;
    asm("cvt.rna.tf32.f32 %0, %1;" : "=r"(r) : "f"(x));
    return r;
}

__device__ __forceinline__ void mma8(float* d,
                                     uint32_t a0, uint32_t a1, uint32_t a2, uint32_t a3,
                                     uint32_t b0, uint32_t b1) {
    asm volatile("mma.sync.aligned.m16n8k8.row.col.f32.tf32.tf32.f32 "
                 "{%0,%1,%2,%3}, {%4,%5,%6,%7}, {%8,%9}, {%0,%1,%2,%3};"
                 : "+f"(d[0]), "+f"(d[1]), "+f"(d[2]), "+f"(d[3])
                 : "r"(a0), "r"(a1), "r"(a2), "r"(a3), "r"(b0), "r"(b1));
}

__device__ __forceinline__ void cpa16(uint32_t daddr, const void* gaddr) {
    asm volatile("cp.async.cg.shared.global [%0], [%1], 16;" :: "r"(daddr), "l"(gaddr));
}
__device__ __forceinline__ void cpa_commit() {
    asm volatile("cp.async.commit_group;" ::: "memory");
}
template <int N>
__device__ __forceinline__ void cpa_wait() {
    asm volatile("cp.async.wait_group %0;" :: "n"(N) : "memory");
}

// ---------------------------------------------------------------------------
// Stage 1: grid 512 (64-row tiles of (b,j)), 128 threads. h read once; loop dirc.
// ---------------------------------------------------------------------------
__global__ __launch_bounds__(128) void ggnn_stage1(const float* __restrict__ h,
                                                   const float* __restrict__ Win,
                                                   const float* __restrict__ Wout) {
    __shared__ uint32_t hs[64 * 68];   // [row][e]
    __shared__ uint32_t wo[64 * 72];   // ws [e][d] stride 72 / outs [lj][p] stride 68
    const int mtile = blockIdx.x;
    const int t = threadIdx.x;
    const int warp = t >> 5, lane = t & 31;
    const int g = lane >> 2, tig = lane & 3;
    const int r0 = warp * 16 + g;

    const float* hbase = h + (size_t)mtile * 64 * 64;
#pragma unroll
    for (int q = 0; q < 8; q++) {
        int f4 = t + q * 128;
        int row = f4 >> 4, e4 = (f4 & 15) * 4;
        float4 v = *(const float4*)(hbase + row * 64 + e4);
        uint4 u = make_uint4(f2tf(v.x), f2tf(v.y), f2tf(v.z), f2tf(v.w));
        *(uint4*)(hs + row * 68 + e4) = u;
    }
    __syncthreads();

    const int b = mtile >> 4;
    const int mtl = mtile & 15;

#pragma unroll 1
    for (int dirc = 0; dirc < 8; dirc++) {
        const float* W = (dirc < 4) ? (Win + dirc * 4096) : (Wout + (dirc - 4) * 4096);
        // ws[e][d] = W[d][e], stride 72
#pragma unroll
        for (int q = 0; q < 8; q++) {
            int f4 = t + q * 128;
            int d = f4 >> 4, e4 = (f4 & 15) * 4;
            float4 v = *(const float4*)(W + d * 64 + e4);
            wo[(e4 + 0) * 72 + d] = f2tf(v.x);
            wo[(e4 + 1) * 72 + d] = f2tf(v.y);
            wo[(e4 + 2) * 72 + d] = f2tf(v.z);
            wo[(e4 + 3) * 72 + d] = f2tf(v.w);
        }
        __syncthreads();

        float acc[8][4];
#pragma unroll
        for (int nt = 0; nt < 8; nt++)
#pragma unroll
            for (int k = 0; k < 4; k++) acc[nt][k] = 0.f;

#pragma unroll
        for (int ks = 0; ks < 8; ks++) {
            int e0 = ks * 8;
            uint32_t a0 = hs[r0 * 68 + e0 + tig];
            uint32_t a1 = hs[(r0 + 8) * 68 + e0 + tig];
            uint32_t a2 = hs[r0 * 68 + e0 + tig + 4];
            uint32_t a3 = hs[(r0 + 8) * 68 + e0 + tig + 4];
#pragma unroll
            for (int nt = 0; nt < 8; nt++) {
                uint32_t b0 = wo[(e0 + tig) * 72 + nt * 8 + g];
                uint32_t b1 = wo[(e0 + tig + 4) * 72 + nt * 8 + g];
                mma8(acc[nt], a0, a1, a2, a3, b0, b1);
            }
        }
        __syncthreads();  // done reading ws

        // stage output tile permuted: outs[lj][p], p = (d&7)*8 + (d>>3)
#pragma unroll
        for (int nt = 0; nt < 8; nt++) {
            wo[r0 * 68 + 16 * tig + nt]           = f2tf(acc[nt][0]);
            wo[r0 * 68 + 16 * tig + 8 + nt]       = f2tf(acc[nt][1]);
            wo[(r0 + 8) * 68 + 16 * tig + nt]     = f2tf(acc[nt][2]);
            wo[(r0 + 8) * 68 + 16 * tig + 8 + nt] = f2tf(acc[nt][3]);
        }
        __syncthreads();

        // dump to blob: [b][dir][ch][kk][64]
        const int dir = dirc >> 2, c = dirc & 3;
        uint32_t* blob = g_scratch + ((size_t)(b * 2 + dir) << 18);
#pragma unroll
        for (int q = 0; q < 8; q++) {
            int idx4 = t + q * 128;          // 1024 16B units
            int lj = idx4 >> 4, u = idx4 & 15;
            int ch = mtl * 4 + (lj >> 4);
            int kk = (lj & 15) * 4 + c;
            uint4 val = *(uint4*)(wo + lj * 68 + u * 4);
            *(uint4*)(blob + (size_t)ch * 4096 + kk * 64 + u * 4) = val;
        }
        __syncthreads();
    }
}

// ---------------------------------------------------------------------------
// Stage 2: grid (8 mtiles, 2 dirs, 32 b), 128 threads (4 warps x 32 rows).
// smem per buffer: gs 64 rows x 68 words (even kk -> rows 0..31, odd -> 32..63),
// adj 2560 words (dir0: [r][jj] stride 20; dir1: [jj][r] stride 132).
// ---------------------------------------------------------------------------
#define GS_W  (64 * 68)                 // 4352
#define AS_W  2560
#define BUF_W (GS_W + AS_W)             // 6912
#define SM2_W (2 * BUF_W)               // 13824 words = 55296 B (dynamic)

__global__ __launch_bounds__(128, 4) void ggnn_stage2(const int* __restrict__ adj,
                                                      const float* __restrict__ bias,
                                                      float* __restrict__ out) {
    extern __shared__ uint32_t sm[];

    const int mtile = blockIdx.x;
    const int dir   = blockIdx.y;
    const int b     = blockIdx.z;
    const int t = threadIdx.x;
    const int warp = t >> 5, lane = t & 31;
    const int g = lane >> 2, tig = lane & 3;
    const int mbase = mtile * 128;
    const int rw = warp * 32;            // warp's first row
    const int ca = (tig & 1) * 2;        // classes ca, ca+1
    const int jb = tig >> 1;             // jj offset 0/1
    const int rs = dir ? 1 : 20;         // adj: v(row,jj) = as_[row*rs + jj*js]
    const int js = dir ? 132 : 1;

    const uint32_t* blob = g_scratch + ((size_t)(b * 2 + dir) << 18);
    const int* adjb = adj + (size_t)b * 1024 * 1024;

    float acc[2][8][4];
#pragma unroll
    for (int rb = 0; rb < 2; rb++)
#pragma unroll
        for (int nt = 0; nt < 8; nt++)
#pragma unroll
            for (int k = 0; k < 4; k++) acc[rb][nt][k] = 0.f;

    auto issue = [&](int ch, int buf) {
        const int j0 = ch * 16;
        uint32_t gdst = (uint32_t)__cvta_generic_to_shared(sm + buf * BUF_W);
        uint32_t adst = gdst + GS_W * 4;
        const uint32_t* gsrc = blob + (size_t)ch * 4096;
        // G chunk: 1024 16B units; row kk -> smem row rr=(kk>>1)+(kk&1)*32, stride 68
#pragma unroll
        for (int q = 0; q < 8; q++) {
            int idx = t + q * 128;
            int kk = idx >> 4, u4 = (idx & 15) * 4;
            int rr = (kk >> 1) + (kk & 1) * 32;
            cpa16(gdst + (rr * 68 + u4) * 4, gsrc + kk * 64 + u4);
        }
        if (dir == 0) {      // [r][jj] stride 20
#pragma unroll
            for (int q = 0; q < 4; q++) {
                int idx = t + q * 128;
                int r = idx >> 2, c4 = (idx & 3) * 4;
                cpa16(adst + (r * 20 + c4) * 4, adjb + (size_t)(mbase + r) * 1024 + j0 + c4);
            }
        } else {             // [jj][r] stride 132
#pragma unroll
            for (int q = 0; q < 4; q++) {
                int idx = t + q * 128;
                int jj = idx >> 5, r4 = (idx & 31) * 4;
                cpa16(adst + (jj * 132 + r4) * 4, adjb + (size_t)(j0 + jj) * 1024 + mbase + r4);
            }
        }
        cpa_commit();
    };

    issue(0, 0);

#pragma unroll 1
    for (int ch = 0; ch < 64; ch++) {
        if (ch < 63) {
            issue(ch + 1, (ch + 1) & 1);
            cpa_wait<1>();
        } else {
            cpa_wait<0>();
        }
        __syncthreads();

        const uint32_t* gs = sm + (ch & 1) * BUF_W;
        const int* as_ = (const int*)(gs + GS_W);

#pragma unroll
        for (int ks = 0; ks < 8; ks++) {
            const int jj = 2 * ks + jb;
            const int* ap = as_ + jj * js + rw * rs;
            int v0 = ap[g * rs];
            int v1 = ap[(g + 8) * rs];
            int v2 = ap[(g + 16) * rs];
            int v3 = ap[(g + 24) * rs];
            uint32_t a00 = (v0 == ca)     ? 0x3F800000u : 0u;
            uint32_t a01 = (v1 == ca)     ? 0x3F800000u : 0u;
            uint32_t a02 = (v0 == ca + 1) ? 0x3F800000u : 0u;
            uint32_t a03 = (v1 == ca + 1) ? 0x3F800000u : 0u;
            uint32_t a10 = (v2 == ca)     ? 0x3F800000u : 0u;
            uint32_t a11 = (v3 == ca)     ? 0x3F800000u : 0u;
            uint32_t a12 = (v2 == ca + 1) ? 0x3F800000u : 0u;
            uint32_t a13 = (v3 == ca + 1) ? 0x3F800000u : 0u;

            // even kk row (b0s) at rr = 4ks+tig; odd kk row (b1s) at +32 rows
            const uint32_t* bpa = gs + (4 * ks + tig) * 68 + 8 * g;
            const uint32_t* bpb = bpa + 32 * 68;
#pragma unroll
            for (int mp = 0; mp < 2; mp++) {
                uint4 B0 = *(const uint4*)(bpa + 4 * mp);   // nt = 4mp..4mp+3, b0
                uint4 B1 = *(const uint4*)(bpb + 4 * mp);   // b1
                mma8(acc[0][4 * mp + 0], a00, a01, a02, a03, B0.x, B1.x);
                mma8(acc[0][4 * mp + 1], a00, a01, a02, a03, B0.y, B1.y);
                mma8(acc[0][4 * mp + 2], a00, a01, a02, a03, B0.z, B1.z);
                mma8(acc[0][4 * mp + 3], a00, a01, a02, a03, B0.w, B1.w);
                mma8(acc[1][4 * mp + 0], a10, a11, a12, a13, B0.x, B1.x);
                mma8(acc[1][4 * mp + 1], a10, a11, a12, a13, B0.y, B1.y);
                mma8(acc[1][4 * mp + 2], a10, a11, a12, a13, B0.z, B1.z);
                mma8(acc[1][4 * mp + 3], a10, a11, a12, a13, B0.w, B1.w);
            }
        }
        __syncthreads();
    }

    // epilogue
#pragma unroll
    for (int rb = 0; rb < 2; rb++) {
        const int i0 = mbase + rw + rb * 16 + g;
#pragma unroll
        for (int nt = 0; nt < 8; nt++) {
            int n = dir * 64 + nt * 8 + tig * 2;
            float2 bv = *(const float2*)(bias + n);
            float* o0 = out + ((size_t)b * 1024 + i0) * 128 + n;
            float* o1 = out + ((size_t)b * 1024 + i0 + 8) * 128 + n;
            *(float2*)o0 = make_float2(acc[rb][nt][0] + bv.x, acc[rb][nt][1] + bv.y);
            *(float2*)o1 = make_float2(acc[rb][nt][2] + bv.x, acc[rb][nt][3] + bv.y);
        }
    }
}

extern "C" void kernel_launch(void* const* d_in, const int* in_sizes, int n_in,
                              void* d_out, int out_size) {
    (void)in_sizes; (void)n_in; (void)out_size;
    const float* h    = (const float*)d_in[0];
    const int*   adj  = (const int*)d_in[1];
    const float* Win  = (const float*)d_in[2];
    const float* Wout = (const float*)d_in[3];
    const float* bias = (const float*)d_in[4];
    float* out = (float*)d_out;

    cudaFuncSetAttribute(ggnn_stage2, cudaFuncAttributeMaxDynamicSharedMemorySize,
                         SM2_W * 4);

    ggnn_stage1<<<512, 128>>>(h, Win, Wout);
    ggnn_stage2<<<dim3(8, 2, 32), 128, SM2_W * 4>>>(adj, bias, out);
}

// round 8
// speedup vs baseline: 3.2814x; 1.7402x over previous
#include <cuda_runtime.h>
#include <cuda_fp16.h>
#include <cstdint>

// GGNN message passing.
// Prep:   wt2[p4][e][n] = tf32(W[dir][c][d][e]), p4=dir*2+a, c=2a+(n>>6), d=n&63.
// Stage1 (tf32 MMA): G[j, dir, c, d] = sum_e h[j,e]*W[dir,c,d,e]; written as fp16x2
//   blob [b][dir][ch][kp][pd]: ch=j>>4, kp=(j&15)*2+a, word=(G_c=2a[d], G_c=2a+1[d]),
//   pd = pi(d) = (d&7)*8+(d>>3)  (pi involution; makes stage2 B reads LDS.128).
// Stage2 (fp16 m16n8k16): out[b,i,dir*64+d] = sum_{j,c} 1[adjX==c]*G + bias.
//   k = jj*4+c; A one-hot synthesized in regs as f16x2 pairs (exact).
//   dir=0: adjX=adj[b,i,j]; dir=1: adjX=adj[b,j,i].

__device__ uint32_t g_scratch[(size_t)8388608];  // 32 MB blob (f16x2 words)
__device__ uint32_t wt2_dev[32768];              // [4][64][128] tf32 bits

__device__ __forceinline__ uint32_t f2tf(float x) {
    uint32_t r;
    asm("cvt.rna.tf32.f32 %0, %1;" : "=r"(r) : "f"(x));
    return r;
}
__device__ __forceinline__ uint32_t pkh2(float lo, float hi) {
    __half2 p = __floats2half2_rn(lo, hi);
    return *(uint32_t*)&p;
}
__device__ __forceinline__ void mma8_tf32(float* d,
                                          uint32_t a0, uint32_t a1, uint32_t a2, uint32_t a3,
                                          uint32_t b0, uint32_t b1) {
    asm volatile("mma.sync.aligned.m16n8k8.row.col.f32.tf32.tf32.f32 "
                 "{%0,%1,%2,%3}, {%4,%5,%6,%7}, {%8,%9}, {%0,%1,%2,%3};"
                 : "+f"(d[0]), "+f"(d[1]), "+f"(d[2]), "+f"(d[3])
                 : "r"(a0), "r"(a1), "r"(a2), "r"(a3), "r"(b0), "r"(b1));
}
__device__ __forceinline__ void mma16_f16(float* d,
                                          uint32_t a0, uint32_t a1, uint32_t a2, uint32_t a3,
                                          uint32_t b0, uint32_t b1) {
    asm volatile("mma.sync.aligned.m16n8k16.row.col.f32.f16.f16.f32 "
                 "{%0,%1,%2,%3}, {%4,%5,%6,%7}, {%8,%9}, {%0,%1,%2,%3};"
                 : "+f"(d[0]), "+f"(d[1]), "+f"(d[2]), "+f"(d[3])
                 : "r"(a0), "r"(a1), "r"(a2), "r"(a3), "r"(b0), "r"(b1));
}
__device__ __forceinline__ void cpa16(uint32_t daddr, const void* gaddr) {
    asm volatile("cp.async.cg.shared.global [%0], [%1], 16;" :: "r"(daddr), "l"(gaddr));
}
__device__ __forceinline__ void cpa_commit() {
    asm volatile("cp.async.commit_group;" ::: "memory");
}
template <int N>
__device__ __forceinline__ void cpa_wait() {
    asm volatile("cp.async.wait_group %0;" :: "n"(N) : "memory");
}

// ---------------------------------------------------------------------------
// Prep: build wt2.  grid 128 x 256 threads.
// ---------------------------------------------------------------------------
__global__ void ggnn_prep(const float* __restrict__ Win, const float* __restrict__ Wout) {
    int idx = blockIdx.x * 256 + threadIdx.x;   // 0..32767
    int p4 = idx >> 13, e = (idx >> 7) & 63, n = idx & 127;
    const float* W = (p4 >> 1) ? Wout : Win;
    int c = 2 * (p4 & 1) + (n >> 6), d = n & 63;
    wt2_dev[idx] = f2tf(W[(c * 64 + d) * 64 + e]);
}

// ---------------------------------------------------------------------------
// Stage 1: grid 512 (64-row (b,j) tiles), 128 thr. tf32 MMA, N=128 per class-pair.
// dyn smem: hs[64*68] + ws[2][64*136] = 21760 words.
// ---------------------------------------------------------------------------
#define S1_SMEM_W (4352 + 2 * 8704)

__global__ __launch_bounds__(128, 2) void ggnn_stage1(const float* __restrict__ h) {
    extern __shared__ uint32_t s1[];
    uint32_t* hs = s1;                       // [row][e] stride 68
    uint32_t* wsb[2] = { s1 + 4352, s1 + 4352 + 8704 };  // [e][n] stride 136

    const int mtile = blockIdx.x;
    const int t = threadIdx.x;
    const int warp = t >> 5, lane = t & 31;
    const int g = lane >> 2, tig = lane & 3;
    const int r0 = warp * 16 + g;

    const float* hbase = h + (size_t)mtile * 64 * 64;
#pragma unroll
    for (int q = 0; q < 8; q++) {
        int f4 = t + q * 128;
        int row = f4 >> 4, e4 = (f4 & 15) * 4;
        float4 v = *(const float4*)(hbase + row * 64 + e4);
        uint4 u = make_uint4(f2tf(v.x), f2tf(v.y), f2tf(v.z), f2tf(v.w));
        *(uint4*)(hs + row * 68 + e4) = u;
    }

    auto issueW = [&](int p4, int buf) {
        uint32_t dst = (uint32_t)__cvta_generic_to_shared(wsb[buf]);
        const uint32_t* src = wt2_dev + p4 * 8192;
#pragma unroll
        for (int q = 0; q < 16; q++) {
            int idx = t + q * 128;               // 2048 u4s
            int e = idx >> 5, n4 = (idx & 31) * 4;
            cpa16(dst + (e * 136 + n4) * 4, src + e * 128 + n4);
        }
        cpa_commit();
    };
    issueW(0, 0);

    const int b = mtile >> 4;
    const int ch = (mtile & 15) * 4 + warp;

#pragma unroll 1
    for (int p4 = 0; p4 < 4; p4++) {
        if (p4 < 3) { issueW(p4 + 1, (p4 + 1) & 1); cpa_wait<1>(); }
        else        { cpa_wait<0>(); }
        __syncthreads();

        const uint32_t* ws = wsb[p4 & 1];
        float acc[16][4];
#pragma unroll
        for (int nt = 0; nt < 16; nt++)
#pragma unroll
            for (int k = 0; k < 4; k++) acc[nt][k] = 0.f;

#pragma unroll
        for (int ks = 0; ks < 8; ks++) {
            int e0 = ks * 8;
            uint32_t a0 = hs[r0 * 68 + e0 + tig];
            uint32_t a1 = hs[(r0 + 8) * 68 + e0 + tig];
            uint32_t a2 = hs[r0 * 68 + e0 + tig + 4];
            uint32_t a3 = hs[(r0 + 8) * 68 + e0 + tig + 4];
#pragma unroll
            for (int nt = 0; nt < 16; nt++) {
                uint32_t b0 = ws[(e0 + tig) * 136 + nt * 8 + g];
                uint32_t b1 = ws[(e0 + tig + 4) * 136 + nt * 8 + g];
                mma8_tf32(acc[nt], a0, a1, a2, a3, b0, b1);
            }
        }

        // direct permuted STG: blob word [ch][kp][pd], pd = 16tig + half*8 + nt
        const int dir = p4 >> 1, a = p4 & 1;
        uint32_t* blob = g_scratch + ((size_t)(b * 2 + dir) << 17);
#pragma unroll
        for (int rb2 = 0; rb2 < 2; rb2++) {      // rows g, g+8
            int kp = 2 * (g + 8 * rb2) + a;
            uint32_t* dst = blob + ch * 2048 + kp * 64 + 16 * tig;
            int i0 = rb2 * 2;
#pragma unroll
            for (int half = 0; half < 2; half++) {   // d even / d odd -> pd +0 / +8
#pragma unroll
                for (int grp = 0; grp < 2; grp++) {  // nt 0-3 / 4-7
                    uint4 u;
                    u.x = pkh2(acc[grp * 4 + 0][i0 + half], acc[grp * 4 + 8][i0 + half]);
                    u.y = pkh2(acc[grp * 4 + 1][i0 + half], acc[grp * 4 + 9][i0 + half]);
                    u.z = pkh2(acc[grp * 4 + 2][i0 + half], acc[grp * 4 + 10][i0 + half]);
                    u.w = pkh2(acc[grp * 4 + 3][i0 + half], acc[grp * 4 + 11][i0 + half]);
                    *(uint4*)(dst + half * 8 + grp * 4) = u;
                }
            }
        }
        __syncthreads();
    }
}

// ---------------------------------------------------------------------------
// Stage 2: grid (8 mtiles, 2 dirs, 32 b), 128 thr (4 warps x 32 rows), fp16 MMA.
// smem buffer: gs 32 kp-rows x 68 + adj 2560 (dir0 [r][jj] s20; dir1 [jj][r] s136).
// ---------------------------------------------------------------------------
#define GS2_W (32 * 68)                  // 2176
#define AS2_W 2560
#define BUF2_W (GS2_W + AS2_W)           // 4736
#define SM2_W (2 * BUF2_W)               // 9472 words = 37888 B (static)

template <int DIR>
__device__ __forceinline__ void stage2_impl(uint32_t* sm,
                                            const int* __restrict__ adj,
                                            const float* __restrict__ bias,
                                            float* __restrict__ out) {
    const int mtile = blockIdx.x;
    const int b     = blockIdx.z;
    const int t = threadIdx.x;
    const int warp = t >> 5, lane = t & 31;
    const int g = lane >> 2, tig = lane & 3;
    const int mbase = mtile * 128;
    const int rw = warp * 32;
    const int ca = 2 * (tig & 1);

    const uint32_t* blob = g_scratch + ((size_t)(b * 2 + DIR) << 17);
    const int* adjb = adj + (size_t)b * 1024 * 1024;

    float acc[2][8][4];
#pragma unroll
    for (int rb = 0; rb < 2; rb++)
#pragma unroll
        for (int nt = 0; nt < 8; nt++)
#pragma unroll
            for (int k = 0; k < 4; k++) acc[rb][nt][k] = 0.f;

    auto issue = [&](int ch, int buf) {
        const int j0 = ch * 16;
        uint32_t gdst = (uint32_t)__cvta_generic_to_shared(sm + buf * BUF2_W);
        uint32_t adst = gdst + GS2_W * 4;
        const uint32_t* gsrc = blob + (size_t)ch * 2048;
#pragma unroll
        for (int q = 0; q < 4; q++) {            // 512 u4s of G
            int idx = t + q * 128;
            int kp = idx >> 4, pd4 = (idx & 15) * 4;
            cpa16(gdst + (kp * 68 + pd4) * 4, gsrc + kp * 64 + pd4);
        }
        if constexpr (DIR == 0) {                // [r][jj] stride 20
#pragma unroll
            for (int q = 0; q < 4; q++) {
                int idx = t + q * 128;
                int r = idx >> 2, c4 = (idx & 3) * 4;
                cpa16(adst + (r * 20 + c4) * 4, adjb + (size_t)(mbase + r) * 1024 + j0 + c4);
            }
        } else {                                 // [jj][r] stride 136
#pragma unroll
            for (int q = 0; q < 4; q++) {
                int idx = t + q * 128;
                int jj = idx >> 5, r4 = (idx & 31) * 4;
                cpa16(adst + (jj * 136 + r4) * 4, adjb + (size_t)(j0 + jj) * 1024 + mbase + r4);
            }
        }
        cpa_commit();
    };

    issue(0, 0);

#pragma unroll 1
    for (int ch = 0; ch < 64; ch++) {
        if (ch < 63) { issue(ch + 1, (ch + 1) & 1); cpa_wait<1>(); }
        else         { cpa_wait<0>(); }
        __syncthreads();

        const uint32_t* gs = sm + (ch & 1) * BUF2_W;
        const int* as_ = (const int*)(gs + GS2_W);
        constexpr int RS = DIR ? 1 : 20;
        constexpr int JS = DIR ? 136 : 1;

#pragma unroll
        for (int ks = 0; ks < 4; ks++) {
            const int jj0 = 4 * ks + (tig >> 1);
            // adj values: rows rw+{g,g+8,g+16,g+24}, jj in {jj0, jj0+2}
            int v00 = as_[(rw + g) * RS + jj0 * JS];
            int v01 = as_[(rw + g + 8) * RS + jj0 * JS];
            int v02 = as_[(rw + g) * RS + (jj0 + 2) * JS];
            int v03 = as_[(rw + g + 8) * RS + (jj0 + 2) * JS];
            int v10 = as_[(rw + g + 16) * RS + jj0 * JS];
            int v11 = as_[(rw + g + 24) * RS + jj0 * JS];
            int v12 = as_[(rw + g + 16) * RS + (jj0 + 2) * JS];
            int v13 = as_[(rw + g + 24) * RS + (jj0 + 2) * JS];
            // f16x2 one-hot pairs: lo = class ca (even k), hi = class ca+1
            uint32_t a00 = (v00 == ca) ? 0x3C00u : ((v00 == ca + 1) ? 0x3C000000u : 0u);
            uint32_t a01 = (v01 == ca) ? 0x3C00u : ((v01 == ca + 1) ? 0x3C000000u : 0u);
            uint32_t a02 = (v02 == ca) ? 0x3C00u : ((v02 == ca + 1) ? 0x3C000000u : 0u);
            uint32_t a03 = (v03 == ca) ? 0x3C00u : ((v03 == ca + 1) ? 0x3C000000u : 0u);
            uint32_t a10 = (v10 == ca) ? 0x3C00u : ((v10 == ca + 1) ? 0x3C000000u : 0u);
            uint32_t a11 = (v11 == ca) ? 0x3C00u : ((v11 == ca + 1) ? 0x3C000000u : 0u);
            uint32_t a12 = (v12 == ca) ? 0x3C00u : ((v12 == ca + 1) ? 0x3C000000u : 0u);
            uint32_t a13 = (v13 == ca) ? 0x3C00u : ((v13 == ca + 1) ? 0x3C000000u : 0u);

            // B: kp rows 8ks+tig (b0) and +4 (b1); pd = 8g + nt
            const uint32_t* bp0 = gs + (8 * ks + tig) * 68 + 8 * g;
            const uint32_t* bp1 = bp0 + 4 * 68;
            uint4 B0a = *(const uint4*)(bp0);
            uint4 B0b = *(const uint4*)(bp0 + 4);
            uint4 B1a = *(const uint4*)(bp1);
            uint4 B1b = *(const uint4*)(bp1 + 4);

            mma16_f16(acc[0][0], a00, a01, a02, a03, B0a.x, B1a.x);
            mma16_f16(acc[0][1], a00, a01, a02, a03, B0a.y, B1a.y);
            mma16_f16(acc[0][2], a00, a01, a02, a03, B0a.z, B1a.z);
            mma16_f16(acc[0][3], a00, a01, a02, a03, B0a.w, B1a.w);
            mma16_f16(acc[0][4], a00, a01, a02, a03, B0b.x, B1b.x);
            mma16_f16(acc[0][5], a00, a01, a02, a03, B0b.y, B1b.y);
            mma16_f16(acc[0][6], a00, a01, a02, a03, B0b.z, B1b.z);
            mma16_f16(acc[0][7], a00, a01, a02, a03, B0b.w, B1b.w);
            mma16_f16(acc[1][0], a10, a11, a12, a13, B0a.x, B1a.x);
            mma16_f16(acc[1][1], a10, a11, a12, a13, B0a.y, B1a.y);
            mma16_f16(acc[1][2], a10, a11, a12, a13, B0a.z, B1a.z);
            mma16_f16(acc[1][3], a10, a11, a12, a13, B0a.w, B1a.w);
            mma16_f16(acc[1][4], a10, a11, a12, a13, B0b.x, B1b.x);
            mma16_f16(acc[1][5], a10, a11, a12, a13, B0b.y, B1b.y);
            mma16_f16(acc[1][6], a10, a11, a12, a13, B0b.z, B1b.z);
            mma16_f16(acc[1][7], a10, a11, a12, a13, B0b.w, B1b.w);
        }
        __syncthreads();
    }

    // epilogue: C col (within dir block) = nt*8 + 2tig (+1)
#pragma unroll
    for (int rb = 0; rb < 2; rb++) {
        const int i0 = mbase + rw + rb * 16 + g;
#pragma unroll
        for (int nt = 0; nt < 8; nt++) {
            int n = DIR * 64 + nt * 8 + tig * 2;
            float2 bv = *(const float2*)(bias + n);
            float* o0 = out + ((size_t)b * 1024 + i0) * 128 + n;
            float* o1 = out + ((size_t)b * 1024 + i0 + 8) * 128 + n;
            *(float2*)o0 = make_float2(acc[rb][nt][0] + bv.x, acc[rb][nt][1] + bv.y);
            *(float2*)o1 = make_float2(acc[rb][nt][2] + bv.x, acc[rb][nt][3] + bv.y);
        }
    }
}

__global__ __launch_bounds__(128, 4) void ggnn_stage2(const int* __restrict__ adj,
                                                      const float* __restrict__ bias,
                                                      float* __restrict__ out) {
    __shared__ uint32_t sm[SM2_W];
    if (blockIdx.y == 0) stage2_impl<0>(sm, adj, bias, out);
    else                 stage2_impl<1>(sm, adj, bias, out);
}

extern "C" void kernel_launch(void* const* d_in, const int* in_sizes, int n_in,
                              void* d_out, int out_size) {
    (void)in_sizes; (void)n_in; (void)out_size;
    const float* h    = (const float*)d_in[0];
    const int*   adj  = (const int*)d_in[1];
    const float* Win  = (const float*)d_in[2];
    const float* Wout = (const float*)d_in[3];
    const float* bias = (const float*)d_in[4];
    float* out = (float*)d_out;

    cudaFuncSetAttribute(ggnn_stage1, cudaFuncAttributeMaxDynamicSharedMemorySize,
                         S1_SMEM_W * 4);

    ggnn_prep<<<128, 256>>>(Win, Wout);
    ggnn_stage1<<<512, 128, S1_SMEM_W * 4>>>(h);
    ggnn_stage2<<<dim3(8, 2, 32), 128>>>(adj, bias, out);
}